// round 15
// baseline (speedup 1.0000x reference)
#include <cuda_runtime.h>
#include <math.h>

// Problem constants
#define BB 2
#define SS 512
#define EE 256
#define HH 8
#define DD 32
#define MM (BB*SS)          // 1024 tokens
#define MAXN 0.99999f       // (1 - 1e-5) / sqrt(C), C = 1
#define EPS15 1e-15f
#define DELTA7 1e-7f

// ---------------- scratch (device globals; no runtime allocation) ----------------
__device__ float g_p0 [MM * 3 * EE];     // qkv GEMM partials (split-K 4)
__device__ float g_p1 [MM * 3 * EE];
__device__ float g_p2 [MM * 3 * EE];
__device__ float g_p3 [MM * 3 * EE];
__device__ float g_q  [MM * EE];
__device__ float g_k  [MM * EE];
__device__ float g_lv [MM * EE];         // logmap0(v), per head
__device__ float g_qn [BB*HH*SS];
__device__ float g_iqn[BB*HH*SS];
__device__ float g_kn [BB*HH*SS];
__device__ float g_ikn[BB*HH*SS];
__device__ float g_avp[4 * BB*HH * SS * DD];  // AV partials per key-split
__device__ float g_rsp[4 * BB*HH * SS];       // row-sum partials per key-split
__device__ float g_tn [BB*HH*SS];        // per-(token,head) tanh(||u||) for out-proj norm
__device__ float g_o0 [MM * EE];         // out-proj partials (split-K 4)
__device__ float g_o1 [MM * EE];
__device__ float g_o2 [MM * EE];
__device__ float g_o3 [MM * EE];

// ---------------- PDL primitives ----------------
__device__ __forceinline__ void pdl_wait()    { asm volatile("griddepcontrol.wait;" ::: "memory"); }
__device__ __forceinline__ void pdl_trigger() { asm volatile("griddepcontrol.launch_dependents;" ::: "memory"); }

// ---------------- reductions ----------------
__device__ __forceinline__ float warp_red(float v) {
#pragma unroll
    for (int o = 16; o; o >>= 1) v += __shfl_xor_sync(0xffffffffu, v, o);
    return v;
}
__device__ __forceinline__ float grp4_red(float v) {
    v += __shfl_xor_sync(0xffffffffu, v, 1);
    v += __shfl_xor_sync(0xffffffffu, v, 2);
    return v;
}
__device__ __forceinline__ float dot4(float4 a, float4 b) {
    return a.x*b.x + a.y*b.y + a.z*b.z + a.w*b.w;
}

#define STR_T(buf, r, c, v4) do { \
    (buf)[((c)+0)*68+(r)] = (v4).x; (buf)[((c)+1)*68+(r)] = (v4).y; \
    (buf)[((c)+2)*68+(r)] = (v4).z; (buf)[((c)+3)*68+(r)] = (v4).w; } while (0)

// ---------------- tf32 mma helpers ----------------
__device__ __forceinline__ unsigned tf32h(float x) {
    unsigned r; asm("cvt.rna.tf32.f32 %0, %1;" : "=r"(r) : "f"(x)); return r;
}
__device__ __forceinline__ unsigned tf32lo(float x, unsigned hi) {
    return tf32h(x - __uint_as_float(hi));
}
__device__ __forceinline__ void mma8(float4& d,
    unsigned a0, unsigned a1, unsigned a2, unsigned a3, unsigned b0, unsigned b1)
{
    asm("mma.sync.aligned.m16n8k8.row.col.f32.tf32.tf32.f32 "
        "{%0,%1,%2,%3},{%4,%5,%6,%7},{%8,%9},{%0,%1,%2,%3};"
        : "+f"(d.x), "+f"(d.y), "+f"(d.z), "+f"(d.w)
        : "r"(a0), "r"(a1), "r"(a2), "r"(a3), "r"(b0), "r"(b1));
}

// ---------------- TF32x3 mma GEMM (QKV), split-K 4, fully unrolled k loop ----------------
// out[r][c] = sum_k A[r][k] * W[c][k]; warp tile 16x32; k-pair permutation
// (logical k-slots {c, c+4} -> physical columns {2c, 2c+1}).
// Each split-z covers k range [z*KSTEPS*8, (z+1)*KSTEPS*8). KSTEPS=8 x 4 splits = K=256.
template<int KSTEPS>
__global__ __launch_bounds__(256) void gemm_tf32(
    const float* __restrict__ A,
    const float* __restrict__ W0, const float* __restrict__ W1, const float* __restrict__ W2,
    float* __restrict__ o0, float* __restrict__ o1,
    float* __restrict__ o2, float* __restrict__ o3, int ldo)
{
    int r0  = blockIdx.x * 64;
    int cg0 = blockIdx.y * 64;
    int wsel = cg0 >> 8;
    const float* W = (wsel == 0) ? W0 : ((wsel == 1) ? W1 : W2);
    int wc0 = cg0 & 255;
    int z = blockIdx.z;
    float* out = (z == 0) ? o0 : (z == 1) ? o1 : (z == 2) ? o2 : o3;
    int kb0 = z * (KSTEPS * 8);

    int lane = threadIdx.x & 31;
    int wid  = threadIdx.x >> 5;
    int wm = (wid & 3) * 16;
    int wn = (wid >> 2) * 32;
    int tq = lane >> 2;
    int tr = lane & 3;

    const float* ap0 = A + (r0 + wm + tq) * 256 + kb0 + 2 * tr;
    const float* ap1 = ap0 + 8 * 256;
    const float* bp  = W + (wc0 + wn + tq) * 256 + kb0 + 2 * tr;

    pdl_wait();

    float4 acc[4] = {};

    float2 a0c = *(const float2*)ap0;
    float2 a1c = *(const float2*)ap1;
    float2 bbc[4];
#pragma unroll
    for (int nt = 0; nt < 4; nt++) bbc[nt] = *(const float2*)(bp + nt * 8 * 256);

#pragma unroll
    for (int ks = 0; ks < KSTEPS; ks++) {
        float2 a0n, a1n, bbn[4];
        if (ks + 1 < KSTEPS) {
            a0n = *(const float2*)(ap0 + (ks + 1) * 8);
            a1n = *(const float2*)(ap1 + (ks + 1) * 8);
#pragma unroll
            for (int nt = 0; nt < 4; nt++)
                bbn[nt] = *(const float2*)(bp + nt * 8 * 256 + (ks + 1) * 8);
        }

        unsigned ah0 = tf32h(a0c.x), ah1 = tf32h(a1c.x), ah2 = tf32h(a0c.y), ah3 = tf32h(a1c.y);
        unsigned al0 = tf32lo(a0c.x, ah0), al1 = tf32lo(a1c.x, ah1);
        unsigned al2 = tf32lo(a0c.y, ah2), al3 = tf32lo(a1c.y, ah3);

#pragma unroll
        for (int nt = 0; nt < 4; nt++) {
            unsigned bh0 = tf32h(bbc[nt].x), bh1 = tf32h(bbc[nt].y);
            unsigned bl0 = tf32lo(bbc[nt].x, bh0), bl1 = tf32lo(bbc[nt].y, bh1);
            mma8(acc[nt], ah0, ah1, ah2, ah3, bl0, bl1);
            mma8(acc[nt], al0, al1, al2, al3, bh0, bh1);
            mma8(acc[nt], ah0, ah1, ah2, ah3, bh0, bh1);
        }
        if (ks + 1 < KSTEPS) {
            a0c = a0n; a1c = a1n;
#pragma unroll
            for (int nt = 0; nt < 4; nt++) bbc[nt] = bbn[nt];
        }
    }

    int orow = r0 + wm + tq;
#pragma unroll
    for (int nt = 0; nt < 4; nt++) {
        int oc = cg0 + wn + nt * 8 + 2 * tr;
        *(float2*)&out[orow * ldo + oc]       = make_float2(acc[nt].x, acc[nt].y);
        *(float2*)&out[(orow + 8) * ldo + oc] = make_float2(acc[nt].z, acc[nt].w);
    }
    pdl_trigger();
}

// ---------------- out-proj GEMM with fused combine (A tile built from avp/rsp) ----------
// grid (16, 4, 4): x = 64-row tile, y = 64 Wo output cols, z = k-split (A cols 64z..64z+63
// = heads 2z, 2z+1). Prologue reconstructs the A tile in smem (normalize + expmap0);
// designated block (y == z) also stores tanh(||u||) per (token,head) to g_tn for post_out.
__global__ __launch_bounds__(256) void gemm_out_fused(
    const float* __restrict__ W,
    float* __restrict__ o0, float* __restrict__ o1,
    float* __restrict__ o2, float* __restrict__ o3)
{
    __shared__ __align__(16) float aS[64 * 68];

    int r0  = blockIdx.x * 64;
    int cg0 = blockIdx.y * 64;
    int z   = blockIdx.z;
    int kb0 = z * 64;
    float* out = (z == 0) ? o0 : (z == 1) ? o1 : (z == 2) ? o2 : o3;

    int lane = threadIdx.x & 31;
    int wid  = threadIdx.x >> 5;

    pdl_wait();   // avp/rsp ready

    // ---- fused combine: build A tile [64 rows][64 cols = 2 heads] ----
    bool writer = (blockIdx.y == (unsigned)z);
#pragma unroll
    for (int i = 0; i < 16; i++) {
        int P = wid * 16 + i;
        int row = P >> 1, hr = P & 1;
        int token = r0 + row;
        int b = token >> 9, s = token & 511;
        int h = 2 * z + hr;
        int bh = b * HH + h;
        float v = 0.f, ss = 0.f;
#pragma unroll
        for (int sp = 0; sp < 4; sp++) {
            v  += g_avp[((size_t)(sp * 16 + bh) * SS + s) * DD + lane];
            ss += g_rsp[(sp * 16 + bh) * SS + s];
        }
        float y = v * __fdividef(1.f, ss);
        float n2 = warp_red(y * y);
        float un = sqrtf(fmaxf(n2, EPS15));
        float th = tanhf(un);
        float f = th / un;
        aS[row * 68 + hr * 32 + lane] = f * y;
        if (writer && lane == 0) g_tn[bh * SS + s] = th;
    }
    __syncthreads();

    // ---- TF32x3 GEMM: A from smem tile (cols 0..63 = k range kb0..kb0+63), B from global
    int wm = (wid & 3) * 16;
    int wn = (wid >> 2) * 32;
    int tq = lane >> 2;
    int tr = lane & 3;

    const float* ap0 = aS + (wm + tq) * 68 + 2 * tr;
    const float* ap1 = ap0 + 8 * 68;
    const float* bp  = W + (cg0 + wn + tq) * 256 + kb0 + 2 * tr;

    float4 acc[4] = {};
#pragma unroll
    for (int ks = 0; ks < 8; ks++) {
        float2 a0c = *(const float2*)(ap0 + ks * 8);
        float2 a1c = *(const float2*)(ap1 + ks * 8);

        unsigned ah0 = tf32h(a0c.x), ah1 = tf32h(a1c.x), ah2 = tf32h(a0c.y), ah3 = tf32h(a1c.y);
        unsigned al0 = tf32lo(a0c.x, ah0), al1 = tf32lo(a1c.x, ah1);
        unsigned al2 = tf32lo(a0c.y, ah2), al3 = tf32lo(a1c.y, ah3);

#pragma unroll
        for (int nt = 0; nt < 4; nt++) {
            float2 bbv = *(const float2*)(bp + nt * 8 * 256 + ks * 8);
            unsigned bh0 = tf32h(bbv.x), bh1 = tf32h(bbv.y);
            unsigned bl0 = tf32lo(bbv.x, bh0), bl1 = tf32lo(bbv.y, bh1);
            mma8(acc[nt], ah0, ah1, ah2, ah3, bl0, bl1);
            mma8(acc[nt], al0, al1, al2, al3, bh0, bh1);
            mma8(acc[nt], ah0, ah1, ah2, ah3, bh0, bh1);
        }
    }

    int orow = r0 + wm + tq;
#pragma unroll
    for (int nt = 0; nt < 4; nt++) {
        int oc = cg0 + wn + nt * 8 + 2 * tr;
        *(float2*)&out[orow * EE + oc]       = make_float2(acc[nt].x, acc[nt].y);
        *(float2*)&out[(orow + 8) * EE + oc] = make_float2(acc[nt].z, acc[nt].w);
    }
    pdl_trigger();
}

// ---------------- per-token QKV postprocess: warp-per-token, shfl-only ----------------
__global__ __launch_bounds__(256) void post_qkv_w(
    const float* __restrict__ x,
    const float* __restrict__ bq, const float* __restrict__ bk, const float* __restrict__ bv)
{
    int wid = threadIdx.x >> 5, lane = threadIdx.x & 31;
    int token = blockIdx.x * 8 + wid;

    // x and biases are external inputs — load before waiting on the GEMM
    const float4* xr = (const float4*)(x + token * EE);
    float4 xa = xr[lane * 2], xb = xr[lane * 2 + 1];
    float xn2 = warp_red(dot4(xa, xa) + dot4(xb, xb));
    float xn = sqrtf(fmaxf(xn2, EPS15));
    float at = atanhf(fminf(xn, 1.f - 1e-5f));   // SC = 1

    int b = token >> 9, s = token & 511;
    int h = lane >> 2;
    int hidx = (b * HH + h) * SS + s;

    pdl_wait();   // GEMM partials ready

#pragma unroll
    for (int w = 0; w < 3; w++) {
        const float* bvec = (w == 0) ? bq : ((w == 1) ? bk : bv);
        size_t off = (size_t)token * (3 * EE) + w * EE;
        const float4* m0 = (const float4*)(g_p0 + off);
        const float4* m1 = (const float4*)(g_p1 + off);
        const float4* m2 = (const float4*)(g_p2 + off);
        const float4* m3 = (const float4*)(g_p3 + off);
        float4 ma = m0[lane*2], mb = m0[lane*2+1];
        float4 t1a = m1[lane*2], t1b = m1[lane*2+1];
        float4 t2a = m2[lane*2], t2b = m2[lane*2+1];
        float4 t3a = m3[lane*2], t3b = m3[lane*2+1];
        ma.x += t1a.x + t2a.x + t3a.x; ma.y += t1a.y + t2a.y + t3a.y;
        ma.z += t1a.z + t2a.z + t3a.z; ma.w += t1a.w + t2a.w + t3a.w;
        mb.x += t1b.x + t2b.x + t3b.x; mb.y += t1b.y + t2b.y + t3b.y;
        mb.z += t1b.z + t2b.z + t3b.z; mb.w += t1b.w + t2b.w + t3b.w;

        const float4* br = (const float4*)bvec;
        float4 ba = br[lane * 2], bb4 = br[lane * 2 + 1];

        float sm2 = warp_red(dot4(ma, ma) + dot4(mb, mb));
        float mxn = sqrtf(fmaxf(sm2, EPS15));
        float factor = tanhf(mxn / xn * at) / mxn;
        float x2 = factor * factor * sm2;
        float xy = warp_red(factor * (dot4(ma, ba) + dot4(mb, bb4)));
        float y2 = warp_red(dot4(ba, ba) + dot4(bb4, bb4));
        float u  = 1.f + 2.f * xy + y2;
        float idn = 1.f / (1.f + 2.f * xy + x2 * y2 + EPS15);
        float c1 = u * factor;
        float c2 = 1.f - x2;

        float r0 = (c1 * ma.x + c2 * ba.x) * idn;
        float r1 = (c1 * ma.y + c2 * ba.y) * idn;
        float r2 = (c1 * ma.z + c2 * ba.z) * idn;
        float r3 = (c1 * ma.w + c2 * ba.w) * idn;
        float r4 = (c1 * mb.x + c2 * bb4.x) * idn;
        float r5 = (c1 * mb.y + c2 * bb4.y) * idn;
        float r6 = (c1 * mb.z + c2 * bb4.z) * idn;
        float r7 = (c1 * mb.w + c2 * bb4.w) * idn;

        if (w < 2) {
            r0 = fminf(r0, MAXN); r1 = fminf(r1, MAXN); r2 = fminf(r2, MAXN); r3 = fminf(r3, MAXN);
            r4 = fminf(r4, MAXN); r5 = fminf(r5, MAXN); r6 = fminf(r6, MAXN); r7 = fminf(r7, MAXN);
            float hn = grp4_red(r0*r0 + r1*r1 + r2*r2 + r3*r3 + r4*r4 + r5*r5 + r6*r6 + r7*r7);
            float4* dst = (float4*)((w == 0 ? g_q : g_k) + token * EE);
            dst[lane * 2]     = make_float4(r0, r1, r2, r3);
            dst[lane * 2 + 1] = make_float4(r4, r5, r6, r7);
            if ((lane & 3) == 0) {
                if (w == 0) { g_qn[hidx] = hn; g_iqn[hidx] = 1.f / (1.f - hn); }
                else        { g_kn[hidx] = hn; g_ikn[hidx] = 1.f / (1.f - hn); }
            }
        } else {
            float vn2 = grp4_red(r0*r0 + r1*r1 + r2*r2 + r3*r3 + r4*r4 + r5*r5 + r6*r6 + r7*r7);
            float vn = sqrtf(fmaxf(vn2, EPS15));
            float lf = atanhf(fminf(vn, 1.f - 1e-5f)) / vn;
            float4* dst = (float4*)(g_lv + token * EE);
            dst[lane * 2]     = make_float4(lf*r0, lf*r1, lf*r2, lf*r3);
            dst[lane * 2 + 1] = make_float4(lf*r4, lf*r5, lf*r6, lf*r7);
        }
    }
    pdl_trigger();
}

// ---------------- fused attention, 4-way key split (2 chunks per CTA) ----------------
#define ATTN_SMEM_BYTES 63488
__global__ __launch_bounds__(256) void attn_fused(const float* __restrict__ hs)
{
    extern __shared__ __align__(16) float sm[];
    float* qT  = sm;
    float* kTb0 = sm + 2176;
    float* kTb1 = sm + 4352;
    float* lv0  = sm + 6528;
    float* lv1  = sm + 8832;
    float* wS   = sm + 11136;
    float* qns  = sm + 15488;
    float* iqs  = sm + 15552;
    float* kns  = sm + 15616;
    float* iks  = sm + 15744;

    int qt = blockIdx.x, sp = blockIdx.y, bh = blockIdx.z;
    int b = bh >> 3, h = bh & 7;
    int q0 = qt * 64;
    int cbase = sp * 128;             // this CTA handles keys [cbase, cbase+128)
    int t = threadIdx.x;
    int ty = t >> 4, tx = t & 15;     // scores mapping
    int ty2 = t >> 3, tx2 = t & 7;    // AV mapping
    int lr0 = t >> 3;
    int lc  = (t & 7) * 4;

    const float* kbase  = g_k  + (size_t)b * SS * EE + h * DD;
    const float* lvbase = g_lv + (size_t)b * SS * EE + h * DD;

    float negcc;
    {
        pdl_wait();   // q/k/lv/norms ready
        negcc = -1.f / (hs[h] * 5.656854249f);
    }

    // prologue: Q tile + first chunk
    {
        float4 q0v = *(const float4*)&g_q[(b * SS + q0 + lr0) * EE + h * DD + lc];
        float4 q1v = *(const float4*)&g_q[(b * SS + q0 + lr0 + 32) * EE + h * DD + lc];
        STR_T(qT, lr0, lc, q0v); STR_T(qT, lr0 + 32, lc, q1v);
        float4 k0v = *(const float4*)&kbase[(cbase + lr0) * EE + lc];
        float4 k1v = *(const float4*)&kbase[(cbase + lr0 + 32) * EE + lc];
        STR_T(kTb0, lr0, lc, k0v); STR_T(kTb0, lr0 + 32, lc, k1v);
        float4 l0v = *(const float4*)&lvbase[(cbase + lr0) * EE + lc];
        float4 l1v = *(const float4*)&lvbase[(cbase + lr0 + 32) * EE + lc];
        *(float4*)&lv0[lr0 * 36 + lc] = l0v;
        *(float4*)&lv0[(lr0 + 32) * 36 + lc] = l1v;
        if (t < 64) {
            qns[t] = g_qn[bh * SS + q0 + t]; iqs[t] = g_iqn[bh * SS + q0 + t];
            kns[t] = g_kn[bh * SS + cbase + t]; iks[t] = g_ikn[bh * SS + cbase + t];
        }
    }
    __syncthreads();

    float av0[4] = {}, av1[4] = {};
    float rs[4] = {};

#pragma unroll
    for (int c = 0; c < 2; c++) {
        int cur = c;
        bool more = (c == 0);
        const float* kT  = cur ? kTb1 : kTb0;
        const float* lvS = cur ? lv1 : lv0;

        float4 k0v, k1v, l0v, l1v; float knv = 0.f, ikv0 = 0.f;
        if (more) {
            int c0n = cbase + 64;
            k0v = *(const float4*)&kbase[(c0n + lr0) * EE + lc];
            k1v = *(const float4*)&kbase[(c0n + lr0 + 32) * EE + lc];
            l0v = *(const float4*)&lvbase[(c0n + lr0) * EE + lc];
            l1v = *(const float4*)&lvbase[(c0n + lr0 + 32) * EE + lc];
            if (t < 64) { knv = g_kn[bh * SS + c0n + t]; ikv0 = g_ikn[bh * SS + c0n + t]; }
        }

        // scores GEMM
        float acc[4][4] = {};
#pragma unroll
        for (int j = 0; j < 32; j++) {
            float4 a  = *(const float4*)&qT[j * 68 + ty * 4];
            float4 bb = *(const float4*)&kT[j * 68 + tx * 4];
            float avr[4] = {a.x, a.y, a.z, a.w};
            float bvr[4] = {bb.x, bb.y, bb.z, bb.w};
#pragma unroll
            for (int i = 0; i < 4; i++)
#pragma unroll
                for (int jj = 0; jj < 4; jj++)
                    acc[i][jj] = fmaf(avr[i], bvr[jj], acc[i][jj]);
        }

        // transform -> unnormalized weights + row-sum partials
        float k2v[4], ikv[4], vfv[4], vf2v[4];
#pragma unroll
        for (int j = 0; j < 4; j++) {
            k2v[j] = kns[cur * 64 + tx * 4 + j];
            ikv[j] = iks[cur * 64 + tx * 4 + j];
            vfv[j] = 1.f - k2v[j];
            vf2v[j] = vfv[j] * vfv[j];
        }
#pragma unroll
        for (int i = 0; i < 4; i++) {
            float q2  = qns[ty * 4 + i];
            float iq2 = 2.f * iqs[ty * 4 + i];
#pragma unroll
            for (int j = 0; j < 4; j++) {
                float xy  = -acc[i][j];
                float t0  = fmaf(2.f, xy, 1.f);
                float u   = t0 + q2;
                float den = fmaf(k2v[j], q2, t0);
                float rd  = __fdividef(1.f, den);
                float num2 = fmaf(u * u, k2v[j], vf2v[j] * q2);
                num2 = fmaf(u * vfv[j], xy + xy, num2);
                float dn  = num2 * rd * rd;
                float am1 = fmaxf(dn * (iq2 * ikv[j]), DELTA7);
                float z   = (1.f + am1) + sqrtf(fmaf(am1, am1, am1 + am1));
                float wv  = exp2f(negcc * __log2f(z));
                rs[i] += wv;
                acc[i][j] = wv;
            }
        }
#pragma unroll
        for (int i = 0; i < 4; i++)
            *(float4*)&wS[(ty * 4 + i) * 68 + tx * 4] =
                make_float4(acc[i][0], acc[i][1], acc[i][2], acc[i][3]);

        if (more) {
            STR_T(kTb1, lr0, lc, k0v); STR_T(kTb1, lr0 + 32, lc, k1v);
            *(float4*)&lv1[lr0 * 36 + lc] = l0v;
            *(float4*)&lv1[(lr0 + 32) * 36 + lc] = l1v;
            if (t < 64) { kns[64 + t] = knv; iks[64 + t] = ikv0; }
        }
        __syncthreads();   // wS + next-chunk tiles visible

        // AV accumulate
        const float* wp0 = &wS[(ty2 * 2) * 68];
        const float* wp1 = wp0 + 68;
        const float* lp  = &lvS[tx2 * 4];
#pragma unroll 8
        for (int cc = 0; cc < 64; cc += 2) {
            float2 wa = *(const float2*)(wp0 + cc);
            float2 wb = *(const float2*)(wp1 + cc);
            float4 l0 = *(const float4*)(lp + cc * 36);
            float4 l1 = *(const float4*)(lp + (cc + 1) * 36);
            av0[0] = fmaf(wa.x, l0.x, av0[0]); av0[0] = fmaf(wa.y, l1.x, av0[0]);
            av0[1] = fmaf(wa.x, l0.y, av0[1]); av0[1] = fmaf(wa.y, l1.y, av0[1]);
            av0[2] = fmaf(wa.x, l0.z, av0[2]); av0[2] = fmaf(wa.y, l1.z, av0[2]);
            av0[3] = fmaf(wa.x, l0.w, av0[3]); av0[3] = fmaf(wa.y, l1.w, av0[3]);
            av1[0] = fmaf(wb.x, l0.x, av1[0]); av1[0] = fmaf(wb.y, l1.x, av1[0]);
            av1[1] = fmaf(wb.x, l0.y, av1[1]); av1[1] = fmaf(wb.y, l1.y, av1[1]);
            av1[2] = fmaf(wb.x, l0.z, av1[2]); av1[2] = fmaf(wb.y, l1.z, av1[2]);
            av1[3] = fmaf(wb.x, l0.w, av1[3]); av1[3] = fmaf(wb.y, l1.w, av1[3]);
        }
        __syncthreads();
    }

    // row-sum reduction across 16 tx lanes (reuse kTb0 as 64x17)
    float* rsS = kTb0;
#pragma unroll
    for (int i = 0; i < 4; i++) rsS[(ty * 4 + i) * 17 + tx] = rs[i];
    __syncthreads();
    if (t < 64) {
        float s = 0.f;
#pragma unroll
        for (int xx = 0; xx < 16; xx++) s += rsS[t * 17 + xx];
        g_rsp[(sp * 16 + bh) * SS + q0 + t] = s;
    }

    // store AV partials (unnormalized)
    {
        size_t base = ((size_t)(sp * 16 + bh) * SS + q0 + 2 * ty2) * DD + tx2 * 4;
        *(float4*)&g_avp[base]      = make_float4(av0[0], av0[1], av0[2], av0[3]);
        *(float4*)&g_avp[base + DD] = make_float4(av1[0], av1[1], av1[2], av1[3]);
    }
    pdl_trigger();
}

// ---------------- final hyp_linear tail: warp-per-token ----------------
__global__ __launch_bounds__(256) void post_out_w(const float* __restrict__ bo, float* __restrict__ out)
{
    int wid = threadIdx.x >> 5, lane = threadIdx.x & 31;
    int token = blockIdx.x * 8 + wid;
    int b = token >> 9, s = token & 511;

    pdl_wait();

    // ||ao_token||^2 = sum_h tanh(||u_h||)^2  (expmap0 norm identity)
    float tnv = (lane < HH) ? g_tn[(b * HH + lane) * SS + s] : 0.f;
    float xn2 = warp_red(tnv * tnv);
    float xn = sqrtf(fmaxf(xn2, EPS15));
    float at = atanhf(fminf(xn, 1.f - 1e-5f));

    size_t off = (size_t)token * EE;
    const float4* m0 = (const float4*)(g_o0 + off);
    const float4* m1 = (const float4*)(g_o1 + off);
    const float4* m2 = (const float4*)(g_o2 + off);
    const float4* m3 = (const float4*)(g_o3 + off);
    float4 ma = m0[lane*2], mb = m0[lane*2+1];
    float4 t1a = m1[lane*2], t1b = m1[lane*2+1];
    float4 t2a = m2[lane*2], t2b = m2[lane*2+1];
    float4 t3a = m3[lane*2], t3b = m3[lane*2+1];
    ma.x += t1a.x + t2a.x + t3a.x; ma.y += t1a.y + t2a.y + t3a.y;
    ma.z += t1a.z + t2a.z + t3a.z; ma.w += t1a.w + t2a.w + t3a.w;
    mb.x += t1b.x + t2b.x + t3b.x; mb.y += t1b.y + t2b.y + t3b.y;
    mb.z += t1b.z + t2b.z + t3b.z; mb.w += t1b.w + t2b.w + t3b.w;

    const float4* br = (const float4*)bo;
    float4 ba = br[lane * 2], bb4 = br[lane * 2 + 1];

    float sm2 = warp_red(dot4(ma, ma) + dot4(mb, mb));
    float mxn = sqrtf(fmaxf(sm2, EPS15));
    float factor = tanhf(mxn / xn * at) / mxn;
    float x2 = factor * factor * sm2;
    float xy = warp_red(factor * (dot4(ma, ba) + dot4(mb, bb4)));
    float y2 = warp_red(dot4(ba, ba) + dot4(bb4, bb4));
    float u  = 1.f + 2.f * xy + y2;
    float idn = 1.f / (1.f + 2.f * xy + x2 * y2 + EPS15);
    float c1 = u * factor;
    float c2 = 1.f - x2;

    float4* dst = (float4*)(out + token * EE);
    dst[lane * 2] = make_float4(
        (c1 * ma.x + c2 * ba.x) * idn, (c1 * ma.y + c2 * ba.y) * idn,
        (c1 * ma.z + c2 * ba.z) * idn, (c1 * ma.w + c2 * ba.w) * idn);
    dst[lane * 2 + 1] = make_float4(
        (c1 * mb.x + c2 * bb4.x) * idn, (c1 * mb.y + c2 * bb4.y) * idn,
        (c1 * mb.z + c2 * bb4.z) * idn, (c1 * mb.w + c2 * bb4.w) * idn);
}

// ---------------- launch (all kernels chained with PDL) ----------------
template<typename K, typename... Args>
static void launch_pdl(K kern, dim3 grid, dim3 block, size_t smem, Args... args)
{
    cudaLaunchConfig_t cfg = {};
    cfg.gridDim = grid;
    cfg.blockDim = block;
    cfg.dynamicSmemBytes = smem;
    cfg.stream = 0;
    cudaLaunchAttribute at[1];
    at[0].id = cudaLaunchAttributeProgrammaticStreamSerialization;
    at[0].val.programmaticStreamSerializationAllowed = 1;
    cfg.attrs = at;
    cfg.numAttrs = 1;
    cudaLaunchKernelEx(&cfg, kern, args...);
}

extern "C" void kernel_launch(void* const* d_in, const int* in_sizes, int n_in,
                              void* d_out, int out_size)
{
    const float* x  = (const float*)d_in[0];
    const float* Wq = (const float*)d_in[1];
    const float* bq = (const float*)d_in[2];
    const float* Wk = (const float*)d_in[3];
    const float* bk = (const float*)d_in[4];
    const float* Wv = (const float*)d_in[5];
    const float* bv = (const float*)d_in[6];
    const float* Wo = (const float*)d_in[7];
    const float* bo = (const float*)d_in[8];
    const float* hs = (const float*)d_in[9];
    float* out = (float*)d_out;

    float *p0, *p1, *p2, *p3, *o0, *o1, *o2, *o3;
    cudaGetSymbolAddress((void**)&p0, g_p0);
    cudaGetSymbolAddress((void**)&p1, g_p1);
    cudaGetSymbolAddress((void**)&p2, g_p2);
    cudaGetSymbolAddress((void**)&p3, g_p3);
    cudaGetSymbolAddress((void**)&o0, g_o0);
    cudaGetSymbolAddress((void**)&o1, g_o1);
    cudaGetSymbolAddress((void**)&o2, g_o2);
    cudaGetSymbolAddress((void**)&o3, g_o3);

    cudaFuncSetAttribute(attn_fused, cudaFuncAttributeMaxDynamicSharedMemorySize, ATTN_SMEM_BYTES);

    launch_pdl(gemm_tf32<8>, dim3(16, 12, 4), dim3(256), 0,
               x, Wq, Wk, Wv, p0, p1, p2, p3, 3 * EE);
    launch_pdl(post_qkv_w, dim3(MM / 8), dim3(256), 0, x, bq, bk, bv);
    launch_pdl(attn_fused, dim3(8, 4, BB * HH), dim3(256), (size_t)ATTN_SMEM_BYTES, hs);
    launch_pdl(gemm_out_fused, dim3(16, 4, 4), dim3(256), 0, Wo, o0, o1, o2, o3);
    launch_pdl(post_out_w, dim3(MM / 8), dim3(256), 0, bo, out);
}

// round 17
// speedup vs baseline: 1.0295x; 1.0295x over previous
#include <cuda_runtime.h>
#include <math.h>

// Problem constants
#define BB 2
#define SS 512
#define EE 256
#define HH 8
#define DD 32
#define MM (BB*SS)          // 1024 tokens
#define MAXN 0.99999f       // (1 - 1e-5) / sqrt(C), C = 1
#define EPS15 1e-15f
#define DELTA7 1e-7f

// ---------------- scratch (device globals; no runtime allocation) ----------------
__device__ float g_p0 [MM * 3 * EE];     // qkv GEMM partials (split-K 4)
__device__ float g_p1 [MM * 3 * EE];
__device__ float g_p2 [MM * 3 * EE];
__device__ float g_p3 [MM * 3 * EE];
__device__ float g_q  [MM * EE];
__device__ float g_k  [MM * EE];
__device__ float g_lv [MM * EE];         // logmap0(v), per head
__device__ float g_qn [BB*HH*SS];
__device__ float g_iqn[BB*HH*SS];
__device__ float g_kn [BB*HH*SS];
__device__ float g_ikn[BB*HH*SS];
__device__ float g_avp[4 * BB*HH * SS * DD];  // AV partials per key-split
__device__ float g_rsp[4 * BB*HH * SS];       // row-sum partials per key-split
__device__ float g_ao [MM * EE];         // attention output (after expmap0)
__device__ float g_o0 [MM * EE];         // out-proj partials (split-K 4)
__device__ float g_o1 [MM * EE];
__device__ float g_o2 [MM * EE];
__device__ float g_o3 [MM * EE];
__device__ unsigned int g_cnt[8 * 16];   // last-CTA-elect counters per (qt,bh); never reset
                                         // (each launch adds exactly 4 -> (old&3)==3 marks last)

// ---------------- PDL primitives ----------------
__device__ __forceinline__ void pdl_wait()    { asm volatile("griddepcontrol.wait;" ::: "memory"); }
__device__ __forceinline__ void pdl_trigger() { asm volatile("griddepcontrol.launch_dependents;" ::: "memory"); }

// ---------------- reductions ----------------
__device__ __forceinline__ float warp_red(float v) {
#pragma unroll
    for (int o = 16; o; o >>= 1) v += __shfl_xor_sync(0xffffffffu, v, o);
    return v;
}
__device__ __forceinline__ float grp4_red(float v) {
    v += __shfl_xor_sync(0xffffffffu, v, 1);
    v += __shfl_xor_sync(0xffffffffu, v, 2);
    return v;
}
__device__ __forceinline__ float dot4(float4 a, float4 b) {
    return a.x*b.x + a.y*b.y + a.z*b.z + a.w*b.w;
}

#define STR_T(buf, r, c, v4) do { \
    (buf)[((c)+0)*68+(r)] = (v4).x; (buf)[((c)+1)*68+(r)] = (v4).y; \
    (buf)[((c)+2)*68+(r)] = (v4).z; (buf)[((c)+3)*68+(r)] = (v4).w; } while (0)

// ---------------- tf32 mma helpers ----------------
__device__ __forceinline__ unsigned tf32h(float x) {
    unsigned r; asm("cvt.rna.tf32.f32 %0, %1;" : "=r"(r) : "f"(x)); return r;
}
__device__ __forceinline__ unsigned tf32lo(float x, unsigned hi) {
    return tf32h(x - __uint_as_float(hi));
}
__device__ __forceinline__ void mma8(float4& d,
    unsigned a0, unsigned a1, unsigned a2, unsigned a3, unsigned b0, unsigned b1)
{
    asm("mma.sync.aligned.m16n8k8.row.col.f32.tf32.tf32.f32 "
        "{%0,%1,%2,%3},{%4,%5,%6,%7},{%8,%9},{%0,%1,%2,%3};"
        : "+f"(d.x), "+f"(d.y), "+f"(d.z), "+f"(d.w)
        : "r"(a0), "r"(a1), "r"(a2), "r"(a3), "r"(b0), "r"(b1));
}

// ---------------- TF32x3 mma GEMM, split-K 4, fully unrolled k loop ----------------
// out[r][c] = sum_k A[r][k] * W[c][k]; warp tile 16x32; k-pair permutation
// (logical k-slots {c, c+4} -> physical columns {2c, 2c+1}).
// Each split-z covers k range [z*KSTEPS*8, (z+1)*KSTEPS*8). KSTEPS=8 x 4 splits = K=256.
template<int KSTEPS>
__global__ __launch_bounds__(256) void gemm_tf32(
    const float* __restrict__ A,
    const float* __restrict__ W0, const float* __restrict__ W1, const float* __restrict__ W2,
    float* __restrict__ o0, float* __restrict__ o1,
    float* __restrict__ o2, float* __restrict__ o3, int ldo)
{
    int r0  = blockIdx.x * 64;
    int cg0 = blockIdx.y * 64;
    int wsel = cg0 >> 8;
    const float* W = (wsel == 0) ? W0 : ((wsel == 1) ? W1 : W2);
    int wc0 = cg0 & 255;
    int z = blockIdx.z;
    float* out = (z == 0) ? o0 : (z == 1) ? o1 : (z == 2) ? o2 : o3;
    int kb0 = z * (KSTEPS * 8);

    int lane = threadIdx.x & 31;
    int wid  = threadIdx.x >> 5;
    int wm = (wid & 3) * 16;
    int wn = (wid >> 2) * 32;
    int tq = lane >> 2;
    int tr = lane & 3;

    const float* ap0 = A + (r0 + wm + tq) * 256 + kb0 + 2 * tr;
    const float* ap1 = ap0 + 8 * 256;
    const float* bp  = W + (wc0 + wn + tq) * 256 + kb0 + 2 * tr;

    pdl_wait();

    float4 acc[4] = {};

    float2 a0c = *(const float2*)ap0;
    float2 a1c = *(const float2*)ap1;
    float2 bbc[4];
#pragma unroll
    for (int nt = 0; nt < 4; nt++) bbc[nt] = *(const float2*)(bp + nt * 8 * 256);

#pragma unroll
    for (int ks = 0; ks < KSTEPS; ks++) {
        float2 a0n, a1n, bbn[4];
        if (ks + 1 < KSTEPS) {
            a0n = *(const float2*)(ap0 + (ks + 1) * 8);
            a1n = *(const float2*)(ap1 + (ks + 1) * 8);
#pragma unroll
            for (int nt = 0; nt < 4; nt++)
                bbn[nt] = *(const float2*)(bp + nt * 8 * 256 + (ks + 1) * 8);
        }

        unsigned ah0 = tf32h(a0c.x), ah1 = tf32h(a1c.x), ah2 = tf32h(a0c.y), ah3 = tf32h(a1c.y);
        unsigned al0 = tf32lo(a0c.x, ah0), al1 = tf32lo(a1c.x, ah1);
        unsigned al2 = tf32lo(a0c.y, ah2), al3 = tf32lo(a1c.y, ah3);

#pragma unroll
        for (int nt = 0; nt < 4; nt++) {
            unsigned bh0 = tf32h(bbc[nt].x), bh1 = tf32h(bbc[nt].y);
            unsigned bl0 = tf32lo(bbc[nt].x, bh0), bl1 = tf32lo(bbc[nt].y, bh1);
            mma8(acc[nt], ah0, ah1, ah2, ah3, bl0, bl1);
            mma8(acc[nt], al0, al1, al2, al3, bh0, bh1);
            mma8(acc[nt], ah0, ah1, ah2, ah3, bh0, bh1);
        }
        if (ks + 1 < KSTEPS) {
            a0c = a0n; a1c = a1n;
#pragma unroll
            for (int nt = 0; nt < 4; nt++) bbc[nt] = bbn[nt];
        }
    }

    int orow = r0 + wm + tq;
#pragma unroll
    for (int nt = 0; nt < 4; nt++) {
        int oc = cg0 + wn + nt * 8 + 2 * tr;
        *(float2*)&out[orow * ldo + oc]       = make_float2(acc[nt].x, acc[nt].y);
        *(float2*)&out[(orow + 8) * ldo + oc] = make_float2(acc[nt].z, acc[nt].w);
    }
    pdl_trigger();
}

// ---------------- per-token QKV postprocess: warp-per-token, shfl-only ----------------
__global__ __launch_bounds__(256) void post_qkv_w(
    const float* __restrict__ x,
    const float* __restrict__ bq, const float* __restrict__ bk, const float* __restrict__ bv)
{
    int wid = threadIdx.x >> 5, lane = threadIdx.x & 31;
    int token = blockIdx.x * 8 + wid;

    // x and biases are external inputs — load before waiting on the GEMM
    const float4* xr = (const float4*)(x + token * EE);
    float4 xa = xr[lane * 2], xb = xr[lane * 2 + 1];
    float xn2 = warp_red(dot4(xa, xa) + dot4(xb, xb));
    float xn = sqrtf(fmaxf(xn2, EPS15));
    float at = atanhf(fminf(xn, 1.f - 1e-5f));   // SC = 1

    int b = token >> 9, s = token & 511;
    int h = lane >> 2;
    int hidx = (b * HH + h) * SS + s;

    pdl_wait();   // GEMM partials ready

#pragma unroll
    for (int w = 0; w < 3; w++) {
        const float* bvec = (w == 0) ? bq : ((w == 1) ? bk : bv);
        size_t off = (size_t)token * (3 * EE) + w * EE;
        const float4* m0 = (const float4*)(g_p0 + off);
        const float4* m1 = (const float4*)(g_p1 + off);
        const float4* m2 = (const float4*)(g_p2 + off);
        const float4* m3 = (const float4*)(g_p3 + off);
        float4 ma = m0[lane*2], mb = m0[lane*2+1];
        float4 t1a = m1[lane*2], t1b = m1[lane*2+1];
        float4 t2a = m2[lane*2], t2b = m2[lane*2+1];
        float4 t3a = m3[lane*2], t3b = m3[lane*2+1];
        ma.x += t1a.x + t2a.x + t3a.x; ma.y += t1a.y + t2a.y + t3a.y;
        ma.z += t1a.z + t2a.z + t3a.z; ma.w += t1a.w + t2a.w + t3a.w;
        mb.x += t1b.x + t2b.x + t3b.x; mb.y += t1b.y + t2b.y + t3b.y;
        mb.z += t1b.z + t2b.z + t3b.z; mb.w += t1b.w + t2b.w + t3b.w;

        const float4* br = (const float4*)bvec;
        float4 ba = br[lane * 2], bb4 = br[lane * 2 + 1];

        float sm2 = warp_red(dot4(ma, ma) + dot4(mb, mb));
        float mxn = sqrtf(fmaxf(sm2, EPS15));
        float factor = tanhf(mxn / xn * at) / mxn;
        float x2 = factor * factor * sm2;
        float xy = warp_red(factor * (dot4(ma, ba) + dot4(mb, bb4)));
        float y2 = warp_red(dot4(ba, ba) + dot4(bb4, bb4));
        float u  = 1.f + 2.f * xy + y2;
        float idn = 1.f / (1.f + 2.f * xy + x2 * y2 + EPS15);
        float c1 = u * factor;
        float c2 = 1.f - x2;

        float r0 = (c1 * ma.x + c2 * ba.x) * idn;
        float r1 = (c1 * ma.y + c2 * ba.y) * idn;
        float r2 = (c1 * ma.z + c2 * ba.z) * idn;
        float r3 = (c1 * ma.w + c2 * ba.w) * idn;
        float r4 = (c1 * mb.x + c2 * bb4.x) * idn;
        float r5 = (c1 * mb.y + c2 * bb4.y) * idn;
        float r6 = (c1 * mb.z + c2 * bb4.z) * idn;
        float r7 = (c1 * mb.w + c2 * bb4.w) * idn;

        if (w < 2) {
            r0 = fminf(r0, MAXN); r1 = fminf(r1, MAXN); r2 = fminf(r2, MAXN); r3 = fminf(r3, MAXN);
            r4 = fminf(r4, MAXN); r5 = fminf(r5, MAXN); r6 = fminf(r6, MAXN); r7 = fminf(r7, MAXN);
            float hn = grp4_red(r0*r0 + r1*r1 + r2*r2 + r3*r3 + r4*r4 + r5*r5 + r6*r6 + r7*r7);
            float4* dst = (float4*)((w == 0 ? g_q : g_k) + token * EE);
            dst[lane * 2]     = make_float4(r0, r1, r2, r3);
            dst[lane * 2 + 1] = make_float4(r4, r5, r6, r7);
            if ((lane & 3) == 0) {
                if (w == 0) { g_qn[hidx] = hn; g_iqn[hidx] = 1.f / (1.f - hn); }
                else        { g_kn[hidx] = hn; g_ikn[hidx] = 1.f / (1.f - hn); }
            }
        } else {
            float vn2 = grp4_red(r0*r0 + r1*r1 + r2*r2 + r3*r3 + r4*r4 + r5*r5 + r6*r6 + r7*r7);
            float vn = sqrtf(fmaxf(vn2, EPS15));
            float lf = atanhf(fminf(vn, 1.f - 1e-5f)) / vn;
            float4* dst = (float4*)(g_lv + token * EE);
            dst[lane * 2]     = make_float4(lf*r0, lf*r1, lf*r2, lf*r3);
            dst[lane * 2 + 1] = make_float4(lf*r4, lf*r5, lf*r6, lf*r7);
        }
    }
    pdl_trigger();
}

// ---------------- fused attention, 4-way key split + last-CTA combine ----------------
#define ATTN_SMEM_BYTES 63488
__global__ __launch_bounds__(256) void attn_fused(const float* __restrict__ hs)
{
    extern __shared__ __align__(16) float sm[];
    float* qT  = sm;
    float* kTb0 = sm + 2176;
    float* kTb1 = sm + 4352;
    float* lv0  = sm + 6528;
    float* lv1  = sm + 8832;
    float* wS   = sm + 11136;
    float* qns  = sm + 15488;
    float* iqs  = sm + 15552;
    float* kns  = sm + 15616;
    float* iks  = sm + 15744;
    __shared__ int sLast;

    int qt = blockIdx.x, sp = blockIdx.y, bh = blockIdx.z;
    int b = bh >> 3, h = bh & 7;
    int q0 = qt * 64;
    int cbase = sp * 128;             // this CTA handles keys [cbase, cbase+128)
    int t = threadIdx.x;
    int ty = t >> 4, tx = t & 15;     // scores mapping
    int ty2 = t >> 3, tx2 = t & 7;    // AV mapping
    int lr0 = t >> 3;
    int lc  = (t & 7) * 4;

    const float* kbase  = g_k  + (size_t)b * SS * EE + h * DD;
    const float* lvbase = g_lv + (size_t)b * SS * EE + h * DD;

    float negcc;
    {
        pdl_wait();   // q/k/lv/norms ready
        negcc = -1.f / (hs[h] * 5.656854249f);
    }

    // prologue: Q tile + first chunk
    {
        float4 q0v = *(const float4*)&g_q[(b * SS + q0 + lr0) * EE + h * DD + lc];
        float4 q1v = *(const float4*)&g_q[(b * SS + q0 + lr0 + 32) * EE + h * DD + lc];
        STR_T(qT, lr0, lc, q0v); STR_T(qT, lr0 + 32, lc, q1v);
        float4 k0v = *(const float4*)&kbase[(cbase + lr0) * EE + lc];
        float4 k1v = *(const float4*)&kbase[(cbase + lr0 + 32) * EE + lc];
        STR_T(kTb0, lr0, lc, k0v); STR_T(kTb0, lr0 + 32, lc, k1v);
        float4 l0v = *(const float4*)&lvbase[(cbase + lr0) * EE + lc];
        float4 l1v = *(const float4*)&lvbase[(cbase + lr0 + 32) * EE + lc];
        *(float4*)&lv0[lr0 * 36 + lc] = l0v;
        *(float4*)&lv0[(lr0 + 32) * 36 + lc] = l1v;
        if (t < 64) {
            qns[t] = g_qn[bh * SS + q0 + t]; iqs[t] = g_iqn[bh * SS + q0 + t];
            kns[t] = g_kn[bh * SS + cbase + t]; iks[t] = g_ikn[bh * SS + cbase + t];
        }
    }
    __syncthreads();

    float av0[4] = {}, av1[4] = {};
    float rs[4] = {};

#pragma unroll
    for (int c = 0; c < 2; c++) {
        int cur = c;
        bool more = (c == 0);
        const float* kT  = cur ? kTb1 : kTb0;
        const float* lvS = cur ? lv1 : lv0;

        float4 k0v, k1v, l0v, l1v; float knv = 0.f, ikv0 = 0.f;
        if (more) {
            int c0n = cbase + 64;
            k0v = *(const float4*)&kbase[(c0n + lr0) * EE + lc];
            k1v = *(const float4*)&kbase[(c0n + lr0 + 32) * EE + lc];
            l0v = *(const float4*)&lvbase[(c0n + lr0) * EE + lc];
            l1v = *(const float4*)&lvbase[(c0n + lr0 + 32) * EE + lc];
            if (t < 64) { knv = g_kn[bh * SS + c0n + t]; ikv0 = g_ikn[bh * SS + c0n + t]; }
        }

        // scores GEMM
        float acc[4][4] = {};
#pragma unroll
        for (int j = 0; j < 32; j++) {
            float4 a  = *(const float4*)&qT[j * 68 + ty * 4];
            float4 bb = *(const float4*)&kT[j * 68 + tx * 4];
            float avr[4] = {a.x, a.y, a.z, a.w};
            float bvr[4] = {bb.x, bb.y, bb.z, bb.w};
#pragma unroll
            for (int i = 0; i < 4; i++)
#pragma unroll
                for (int jj = 0; jj < 4; jj++)
                    acc[i][jj] = fmaf(avr[i], bvr[jj], acc[i][jj]);
        }

        // transform -> unnormalized weights + row-sum partials
        float k2v[4], ikv[4], vfv[4], vf2v[4];
#pragma unroll
        for (int j = 0; j < 4; j++) {
            k2v[j] = kns[cur * 64 + tx * 4 + j];
            ikv[j] = iks[cur * 64 + tx * 4 + j];
            vfv[j] = 1.f - k2v[j];
            vf2v[j] = vfv[j] * vfv[j];
        }
#pragma unroll
        for (int i = 0; i < 4; i++) {
            float q2  = qns[ty * 4 + i];
            float iq2 = 2.f * iqs[ty * 4 + i];
#pragma unroll
            for (int j = 0; j < 4; j++) {
                float xy  = -acc[i][j];
                float t0  = fmaf(2.f, xy, 1.f);
                float u   = t0 + q2;
                float den = fmaf(k2v[j], q2, t0);
                float rd  = __fdividef(1.f, den);
                float num2 = fmaf(u * u, k2v[j], vf2v[j] * q2);
                num2 = fmaf(u * vfv[j], xy + xy, num2);
                float dn  = num2 * rd * rd;
                float am1 = fmaxf(dn * (iq2 * ikv[j]), DELTA7);
                float z   = (1.f + am1) + sqrtf(fmaf(am1, am1, am1 + am1));
                float wv  = exp2f(negcc * __log2f(z));
                rs[i] += wv;
                acc[i][j] = wv;
            }
        }
#pragma unroll
        for (int i = 0; i < 4; i++)
            *(float4*)&wS[(ty * 4 + i) * 68 + tx * 4] =
                make_float4(acc[i][0], acc[i][1], acc[i][2], acc[i][3]);

        if (more) {
            STR_T(kTb1, lr0, lc, k0v); STR_T(kTb1, lr0 + 32, lc, k1v);
            *(float4*)&lv1[lr0 * 36 + lc] = l0v;
            *(float4*)&lv1[(lr0 + 32) * 36 + lc] = l1v;
            if (t < 64) { kns[64 + t] = knv; iks[64 + t] = ikv0; }
        }
        __syncthreads();   // wS + next-chunk tiles visible

        // AV accumulate
        const float* wp0 = &wS[(ty2 * 2) * 68];
        const float* wp1 = wp0 + 68;
        const float* lp  = &lvS[tx2 * 4];
#pragma unroll 8
        for (int cc = 0; cc < 64; cc += 2) {
            float2 wa = *(const float2*)(wp0 + cc);
            float2 wb = *(const float2*)(wp1 + cc);
            float4 l0 = *(const float4*)(lp + cc * 36);
            float4 l1 = *(const float4*)(lp + (cc + 1) * 36);
            av0[0] = fmaf(wa.x, l0.x, av0[0]); av0[0] = fmaf(wa.y, l1.x, av0[0]);
            av0[1] = fmaf(wa.x, l0.y, av0[1]); av0[1] = fmaf(wa.y, l1.y, av0[1]);
            av0[2] = fmaf(wa.x, l0.z, av0[2]); av0[2] = fmaf(wa.y, l1.z, av0[2]);
            av0[3] = fmaf(wa.x, l0.w, av0[3]); av0[3] = fmaf(wa.y, l1.w, av0[3]);
            av1[0] = fmaf(wb.x, l0.x, av1[0]); av1[0] = fmaf(wb.y, l1.x, av1[0]);
            av1[1] = fmaf(wb.x, l0.y, av1[1]); av1[1] = fmaf(wb.y, l1.y, av1[1]);
            av1[2] = fmaf(wb.x, l0.z, av1[2]); av1[2] = fmaf(wb.y, l1.z, av1[2]);
            av1[3] = fmaf(wb.x, l0.w, av1[3]); av1[3] = fmaf(wb.y, l1.w, av1[3]);
        }
        __syncthreads();
    }

    // row-sum reduction across 16 tx lanes (reuse kTb0 as 64x17)
    float* rsS = kTb0;
#pragma unroll
    for (int i = 0; i < 4; i++) rsS[(ty * 4 + i) * 17 + tx] = rs[i];
    __syncthreads();
    if (t < 64) {
        float s = 0.f;
#pragma unroll
        for (int xx = 0; xx < 16; xx++) s += rsS[t * 17 + xx];
        g_rsp[(sp * 16 + bh) * SS + q0 + t] = s;
    }

    // store AV partials (unnormalized)
    {
        size_t base = ((size_t)(sp * 16 + bh) * SS + q0 + 2 * ty2) * DD + tx2 * 4;
        *(float4*)&g_avp[base]      = make_float4(av0[0], av0[1], av0[2], av0[3]);
        *(float4*)&g_avp[base + DD] = make_float4(av1[0], av1[1], av1[2], av1[3]);
    }

    // ---- last-CTA-elect combine (threadFenceReduction pattern) ----
    __threadfence();           // make this CTA's partials globally visible
    __syncthreads();
    if (t == 0) {
        unsigned old = atomicAdd(&g_cnt[qt * 16 + bh], 1u);
        sLast = ((old & 3u) == 3u);
    }
    __syncthreads();
    if (sLast) {
        __threadfence();       // acquire side: other CTAs' partials now visible
        int wid = t >> 5, lane = t & 31;
#pragma unroll
        for (int rr = 0; rr < 8; rr++) {
            int q = q0 + wid * 8 + rr;
            float v = 0.f, s = 0.f;
#pragma unroll
            for (int p = 0; p < 4; p++) {
                v += g_avp[((size_t)(p * 16 + bh) * SS + q) * DD + lane];
                s += g_rsp[(p * 16 + bh) * SS + q];
            }
            float y = v * __fdividef(1.f, s);
            float n2 = warp_red(y * y);
            float un = sqrtf(fmaxf(n2, EPS15));
            float f = tanhf(un) / un;   // SC = 1
            g_ao[(b * SS + q) * EE + h * DD + lane] = f * y;
        }
    }
    pdl_trigger();
}

// ---------------- final hyp_linear tail: warp-per-token ----------------
__global__ __launch_bounds__(256) void post_out_w(const float* __restrict__ bo, float* __restrict__ out)
{
    int wid = threadIdx.x >> 5, lane = threadIdx.x & 31;
    int token = blockIdx.x * 8 + wid;

    pdl_wait();

    const float4* xr = (const float4*)(g_ao + token * EE);
    float4 xa = xr[lane * 2], xb = xr[lane * 2 + 1];
    float xn2 = warp_red(dot4(xa, xa) + dot4(xb, xb));
    float xn = sqrtf(fmaxf(xn2, EPS15));
    float at = atanhf(fminf(xn, 1.f - 1e-5f));

    size_t off = (size_t)token * EE;
    const float4* m0 = (const float4*)(g_o0 + off);
    const float4* m1 = (const float4*)(g_o1 + off);
    const float4* m2 = (const float4*)(g_o2 + off);
    const float4* m3 = (const float4*)(g_o3 + off);
    float4 ma = m0[lane*2], mb = m0[lane*2+1];
    float4 t1a = m1[lane*2], t1b = m1[lane*2+1];
    float4 t2a = m2[lane*2], t2b = m2[lane*2+1];
    float4 t3a = m3[lane*2], t3b = m3[lane*2+1];
    ma.x += t1a.x + t2a.x + t3a.x; ma.y += t1a.y + t2a.y + t3a.y;
    ma.z += t1a.z + t2a.z + t3a.z; ma.w += t1a.w + t2a.w + t3a.w;
    mb.x += t1b.x + t2b.x + t3b.x; mb.y += t1b.y + t2b.y + t3b.y;
    mb.z += t1b.z + t2b.z + t3b.z; mb.w += t1b.w + t2b.w + t3b.w;

    const float4* br = (const float4*)bo;
    float4 ba = br[lane * 2], bb4 = br[lane * 2 + 1];

    float sm2 = warp_red(dot4(ma, ma) + dot4(mb, mb));
    float mxn = sqrtf(fmaxf(sm2, EPS15));
    float factor = tanhf(mxn / xn * at) / mxn;
    float x2 = factor * factor * sm2;
    float xy = warp_red(factor * (dot4(ma, ba) + dot4(mb, bb4)));
    float y2 = warp_red(dot4(ba, ba) + dot4(bb4, bb4));
    float u  = 1.f + 2.f * xy + y2;
    float idn = 1.f / (1.f + 2.f * xy + x2 * y2 + EPS15);
    float c1 = u * factor;
    float c2 = 1.f - x2;

    float4* dst = (float4*)(out + token * EE);
    dst[lane * 2] = make_float4(
        (c1 * ma.x + c2 * ba.x) * idn, (c1 * ma.y + c2 * ba.y) * idn,
        (c1 * ma.z + c2 * ba.z) * idn, (c1 * ma.w + c2 * ba.w) * idn);
    dst[lane * 2 + 1] = make_float4(
        (c1 * mb.x + c2 * bb4.x) * idn, (c1 * mb.y + c2 * bb4.y) * idn,
        (c1 * mb.z + c2 * bb4.z) * idn, (c1 * mb.w + c2 * bb4.w) * idn);
}

// ---------------- launch (all kernels chained with PDL) ----------------
template<typename K, typename... Args>
static void launch_pdl(K kern, dim3 grid, dim3 block, size_t smem, Args... args)
{
    cudaLaunchConfig_t cfg = {};
    cfg.gridDim = grid;
    cfg.blockDim = block;
    cfg.dynamicSmemBytes = smem;
    cfg.stream = 0;
    cudaLaunchAttribute at[1];
    at[0].id = cudaLaunchAttributeProgrammaticStreamSerialization;
    at[0].val.programmaticStreamSerializationAllowed = 1;
    cfg.attrs = at;
    cfg.numAttrs = 1;
    cudaLaunchKernelEx(&cfg, kern, args...);
}

extern "C" void kernel_launch(void* const* d_in, const int* in_sizes, int n_in,
                              void* d_out, int out_size)
{
    const float* x  = (const float*)d_in[0];
    const float* Wq = (const float*)d_in[1];
    const float* bq = (const float*)d_in[2];
    const float* Wk = (const float*)d_in[3];
    const float* bk = (const float*)d_in[4];
    const float* Wv = (const float*)d_in[5];
    const float* bv = (const float*)d_in[6];
    const float* Wo = (const float*)d_in[7];
    const float* bo = (const float*)d_in[8];
    const float* hs = (const float*)d_in[9];
    float* out = (float*)d_out;

    float *p0, *p1, *p2, *p3, *o0, *o1, *o2, *o3, *ao;
    cudaGetSymbolAddress((void**)&p0, g_p0);
    cudaGetSymbolAddress((void**)&p1, g_p1);
    cudaGetSymbolAddress((void**)&p2, g_p2);
    cudaGetSymbolAddress((void**)&p3, g_p3);
    cudaGetSymbolAddress((void**)&o0, g_o0);
    cudaGetSymbolAddress((void**)&o1, g_o1);
    cudaGetSymbolAddress((void**)&o2, g_o2);
    cudaGetSymbolAddress((void**)&o3, g_o3);
    cudaGetSymbolAddress((void**)&ao, g_ao);

    cudaFuncSetAttribute(attn_fused, cudaFuncAttributeMaxDynamicSharedMemorySize, ATTN_SMEM_BYTES);

    launch_pdl(gemm_tf32<8>, dim3(16, 12, 4), dim3(256), 0,
               x, Wq, Wk, Wv, p0, p1, p2, p3, 3 * EE);
    launch_pdl(post_qkv_w, dim3(MM / 8), dim3(256), 0, x, bq, bk, bv);
    launch_pdl(attn_fused, dim3(8, 4, BB * HH), dim3(256), (size_t)ATTN_SMEM_BYTES, hs);
    launch_pdl(gemm_tf32<8>, dim3(16, 4, 4), dim3(256), 0,
               (const float*)ao, Wo, Wo, Wo, o0, o1, o2, o3, EE);
    launch_pdl(post_out_w, dim3(MM / 8), dim3(256), 0, bo, out);
}